// round 6
// baseline (speedup 1.0000x reference)
#include <cuda_runtime.h>
#include <math.h>

// Shapes fixed by setup_inputs(): B=64, S=256, H=768, D=64, NEG=4
// Inputs: encoded[B,S,H] f32, n_encoded[B*NEG,S,H] f32,
//         mask1[B,S,1], mask2[B,S,1], mask_u_neg[B*NEG,S,1], W[D,H]
// Output: scalar float loss.
//
// One block per batch. Vectorized datapath: LDG.128 / LDS.128 + packed
// fma.rn.f32x2 (sm_103a) so the 6-vector shared matvec issues ~2.3x fewer
// instructions than the scalar version (issue-bound per ncu R5).

#define PB_EPS 1e-15f
#define PB_BND (1.0f - 1e-7f)

#define PB_B   64
#define PB_S   256
#define PB_H   768
#define PB_D   64
#define PB_NEG 4
#define PB_H4  (PB_H / 4)   // 192 float4 / ulonglong2 chunks per row

typedef unsigned long long u64;

__device__ __forceinline__ float warp_sum(float v) {
#pragma unroll
    for (int o = 16; o; o >>= 1) v += __shfl_xor_sync(0xffffffffu, v, o);
    return v;
}

// packed dual-fp32 FMA (Blackwell f32x2 pipe; exact 2x IEEE fmaf)
__device__ __forceinline__ void fma_x2(u64& d, u64 a, u64 b, u64 c) {
    asm("fma.rn.f32x2 %0, %1, %2, %3;" : "=l"(d) : "l"(a), "l"(b), "l"(c));
}

__device__ __forceinline__ float x2_hsum(u64 a) {
    float2 f = *reinterpret_cast<float2*>(&a);
    return f.x + f.y;
}

// 2 * artanh(|| mobius_add(-u, w) ||), vectors split 2 elems/lane (D=64).
__device__ __forceinline__ float pb_dist(
    float u0, float u1, float w0, float w1, float x2, float y2, float duw)
{
    float xy  = -duw;
    float ca  = 1.f + 2.f * xy + y2;   // coefficient of (-u)
    float cb  = 1.f - x2;              // coefficient of w
    float n0  = ca * (-u0) + cb * w0;
    float n1  = ca * (-u1) + cb * w1;
    float nn  = warp_sum(n0 * n0 + n1 * n1);
    float den = fmaxf(1.f + 2.f * xy + x2 * y2, PB_EPS);
    float arg = sqrtf(nn) / den;
    return 2.f * atanhf(fminf(arg, PB_BND));
}

__global__ __launch_bounds__(256, 1)
void pb_fused_kernel(const float* __restrict__ encoded,
                     const float* __restrict__ n_encoded,
                     const float* __restrict__ mask1,
                     const float* __restrict__ mask2,
                     const float* __restrict__ mask_neg,
                     const float* __restrict__ W,
                     float* __restrict__ out)
{
    const int b    = blockIdx.x;
    const int tid  = threadIdx.x;
    const int wid  = tid >> 5;
    const int lane = tid & 31;

    __shared__ int   s_pos[6];
    __shared__ float4 xs4[6][PB_H4];   // gathered raw token vectors (16B chunks)
    __shared__ float s_part[8][6];     // per-warp partial sum-of-squares
    __shared__ float s_scale[6];       // expmap0 scale tanh(n)/n
    __shared__ float s_xn[6];          // clip(||y||, EPS)
    __shared__ float mxs[6][PB_D];     // matvec results -> final vectors
    __shared__ float s_term[6];        // e_neg0..3, e_pos, angle

    // ---- 1. one-hot position lookup (S == blockDim) ----
    if (mask1[(size_t)b * PB_S + tid] > 0.5f) s_pos[0] = tid;
    if (mask2[(size_t)b * PB_S + tid] > 0.5f) s_pos[1] = tid;
#pragma unroll
    for (int k = 0; k < PB_NEG; k++)
        if (mask_neg[(size_t)(b * PB_NEG + k) * PB_S + tid] > 0.5f) s_pos[2 + k] = tid;
    __syncthreads();

    // ---- 2. gather 6 rows (float4) into smem + sum of squares ----
    const float4* xrow[6];
    xrow[0] = (const float4*)(encoded + ((size_t)b * PB_S + s_pos[0]) * PB_H);
    xrow[1] = (const float4*)(encoded + ((size_t)b * PB_S + s_pos[1]) * PB_H);
#pragma unroll
    for (int k = 0; k < PB_NEG; k++)
        xrow[2 + k] = (const float4*)(n_encoded +
                      ((size_t)(b * PB_NEG + k) * PB_S + s_pos[2 + k]) * PB_H);

    float ss[6] = {0.f, 0.f, 0.f, 0.f, 0.f, 0.f};
    if (tid < PB_H4) {
#pragma unroll
        for (int j = 0; j < 6; j++) {
            float4 v = xrow[j][tid];
            xs4[j][tid] = v;
            ss[j] += v.x * v.x + v.y * v.y + v.z * v.z + v.w * v.w;
        }
    }
#pragma unroll
    for (int j = 0; j < 6; j++) ss[j] = warp_sum(ss[j]);
    if (lane == 0) {
#pragma unroll
        for (int j = 0; j < 6; j++) s_part[wid][j] = ss[j];
    }
    __syncthreads();

    // ---- 3. expmap0 scales ----
    if (wid == 0 && lane < 6) {
        float t = 0.f;
#pragma unroll
        for (int w = 0; w < 8; w++) t += s_part[w][lane];
        float nrm = sqrtf(t);
        float ncl = fmaxf(nrm, PB_EPS);
        float sc  = tanhf(ncl) / ncl;
        s_scale[lane] = sc;
        s_xn[lane]    = fmaxf(sc * nrm, PB_EPS);
    }
    __syncthreads();

    // ---- 4. shared matvec, vectorized: warp w -> dims [w*8, w*8+8),
    //         processed in 2 groups of 4 dims so xs LDS.128 amortize x4. ----
    const ulonglong2* Wu = (const ulonglong2*)W;           // [D][H4]
    const ulonglong2* xu[6];
#pragma unroll
    for (int j = 0; j < 6; j++) xu[j] = (const ulonglong2*)xs4[j];

#pragma unroll
    for (int dg = 0; dg < 2; dg++) {
        const int dbase = wid * 8 + dg * 4;
        u64 acc[4][6];
#pragma unroll
        for (int dd = 0; dd < 4; dd++)
#pragma unroll
            for (int j = 0; j < 6; j++) acc[dd][j] = 0ull;

#pragma unroll
        for (int i = 0; i < PB_H4 / 32; i++) {             // 6 iterations
            const int c = lane + i * 32;
            ulonglong2 xv[6];
#pragma unroll
            for (int j = 0; j < 6; j++) xv[j] = xu[j][c];  // LDS.128
#pragma unroll
            for (int dd = 0; dd < 4; dd++) {
                ulonglong2 wv = Wu[(size_t)(dbase + dd) * PB_H4 + c];  // LDG.128
#pragma unroll
                for (int j = 0; j < 6; j++) {
                    fma_x2(acc[dd][j], wv.x, xv[j].x, acc[dd][j]);
                    fma_x2(acc[dd][j], wv.y, xv[j].y, acc[dd][j]);
                }
            }
        }

#pragma unroll
        for (int dd = 0; dd < 4; dd++) {
            float r0 = warp_sum(x2_hsum(acc[dd][0]));
            float r1 = warp_sum(x2_hsum(acc[dd][1]));
            float r2 = warp_sum(x2_hsum(acc[dd][2]));
            float r3 = warp_sum(x2_hsum(acc[dd][3]));
            float r4 = warp_sum(x2_hsum(acc[dd][4]));
            float r5 = warp_sum(x2_hsum(acc[dd][5]));
            if (lane == 0) {
                mxs[0][dbase + dd] = r0 * s_scale[0];
                mxs[1][dbase + dd] = r1 * s_scale[1];
                mxs[2][dbase + dd] = r2 * s_scale[2];
                mxs[3][dbase + dd] = r3 * s_scale[3];
                mxs[4][dbase + dd] = r4 * s_scale[4];
                mxs[5][dbase + dd] = r5 * s_scale[5];
            }
        }
    }
    __syncthreads();

    // ---- 5. mobius_matvec rescale, in place (6 warps in parallel) ----
    if (wid < 6) {
        float m0 = mxs[wid][lane];
        float m1 = mxs[wid][lane + 32];
        float t  = warp_sum(m0 * m0 + m1 * m1);
        float mn = fmaxf(sqrtf(t), PB_EPS);
        float xn = s_xn[wid];
        float fac = tanhf(mn / xn * atanhf(fminf(xn, PB_BND))) / mn;
        mxs[wid][lane]      = m0 * fac;
        mxs[wid][lane + 32] = m1 * fac;
    }
    __syncthreads();

    // ---- 6. epilogue: 6 warps compute angle + 5 distances in parallel ----
    float u0  = mxs[0][lane];
    float u1  = mxs[0][lane + 32];
    float nu2 = warp_sum(u0 * u0 + u1 * u1);

    if (wid < 4) {                      // negative distances
        float w0 = mxs[2 + wid][lane];
        float w1 = mxs[2 + wid][lane + 32];
        float y2 = warp_sum(w0 * w0 + w1 * w1);
        float dn = warp_sum(u0 * w0 + u1 * w1);
        float dk = pb_dist(u0, u1, w0, w1, nu2, y2, dn);
        if (lane == 0) s_term[wid] = expf(-dk);
    } else if (wid == 4) {              // positive-pair distance
        float v0  = mxs[1][lane];
        float v1  = mxs[1][lane + 32];
        float nv2 = warp_sum(v0 * v0 + v1 * v1);
        float duv = warp_sum(u0 * v0 + u1 * v1);
        float dp  = pb_dist(u0, u1, v0, v1, nu2, nv2, duv);
        if (lane == 0) s_term[4] = expf(-dp);
    } else if (wid == 5) {              // angle term
        float v0  = mxs[1][lane];
        float v1  = mxs[1][lane + 32];
        float nv2 = warp_sum(v0 * v0 + v1 * v1);
        float duv = warp_sum(u0 * v0 + u1 * v1);
        float d0  = u0 - v0, d1 = u1 - v1;
        float e2  = warp_sum(d0 * d0 + d1 * d1);
        float norm_v = sqrtf(nv2);
        float euclid = sqrtf(e2);
        float rad = fmaxf(1.f + nu2 * nv2 - 2.f * duv, PB_EPS);
        float den = fmaxf(norm_v * euclid * sqrtf(rad), PB_EPS);
        float ca  = (duv * (1.f + nv2) - nv2 * (1.f + nu2)) / den;
        ca = fminf(fmaxf(ca, -PB_BND), PB_BND);
        if (lane == 0) s_term[5] = acosf(ca);
    }
    __syncthreads();

    // ---- 7. combine + accumulate mean (alpha=0.5 => both weights are 1) ----
    if (tid == 0) {
        float Z1 = s_term[0] + s_term[1] + s_term[2] + s_term[3];
        float ep = s_term[4];
        float ns = -logf(ep / (Z1 + ep));
        atomicAdd(out, (s_term[5] + ns) * (1.0f / PB_B));
    }
}

extern "C" void kernel_launch(void* const* d_in, const int* in_sizes, int n_in,
                              void* d_out, int out_size)
{
    const float* encoded   = (const float*)d_in[0];
    const float* n_encoded = (const float*)d_in[1];
    const float* mask1     = (const float*)d_in[2];
    const float* mask2     = (const float*)d_in[3];
    const float* mask_neg  = (const float*)d_in[4];
    const float* W         = (const float*)d_in[5];
    float* out = (float*)d_out;

    cudaMemsetAsync(out, 0, sizeof(float));
    pb_fused_kernel<<<PB_B, 256>>>(encoded, n_encoded,
                                   mask1, mask2, mask_neg, W, out);
}

// round 7
// speedup vs baseline: 1.0489x; 1.0489x over previous
#include <cuda_runtime.h>
#include <math.h>

// Shapes fixed by setup_inputs(): B=64, S=256, H=768, D=64, NEG=4
// Inputs: encoded[B,S,H] f32, n_encoded[B*NEG,S,H] f32,
//         mask1[B,S,1], mask2[B,S,1], mask_u_neg[B*NEG,S,1], W[D,H]
// Output: scalar float loss.
//
// One block per batch, 512 threads (16 warps). Warp w computes output dims
// [w*4, w*4+4) for all 6 vectors (u, v, 4 negs) -> halves per-warp serial
// matvec work vs R6 and doubles warps/SMSP for latency hiding (R6 ncu:
// occ 12.8%, issue 24%, regs 255 => latency-bound with spills).

#define PB_EPS 1e-15f
#define PB_BND (1.0f - 1e-7f)

#define PB_B   64
#define PB_S   256
#define PB_H   768
#define PB_D   64
#define PB_NEG 4
#define PB_H4  (PB_H / 4)   // 192 16B chunks per row

typedef unsigned long long u64;

__device__ __forceinline__ float warp_sum(float v) {
#pragma unroll
    for (int o = 16; o; o >>= 1) v += __shfl_xor_sync(0xffffffffu, v, o);
    return v;
}

// packed dual-fp32 FMA (Blackwell f32x2; exact 2x IEEE fmaf)
__device__ __forceinline__ void fma_x2(u64& d, u64 a, u64 b, u64 c) {
    asm("fma.rn.f32x2 %0, %1, %2, %3;" : "=l"(d) : "l"(a), "l"(b), "l"(c));
}

__device__ __forceinline__ float x2_hsum(u64 a) {
    float2 f = *reinterpret_cast<float2*>(&a);
    return f.x + f.y;
}

// 2 * artanh(|| mobius_add(-u, w) ||), vectors split 2 elems/lane (D=64).
__device__ __forceinline__ float pb_dist(
    float u0, float u1, float w0, float w1, float x2, float y2, float duw)
{
    float xy  = -duw;
    float ca  = 1.f + 2.f * xy + y2;   // coefficient of (-u)
    float cb  = 1.f - x2;              // coefficient of w
    float n0  = ca * (-u0) + cb * w0;
    float n1  = ca * (-u1) + cb * w1;
    float nn  = warp_sum(n0 * n0 + n1 * n1);
    float den = fmaxf(1.f + 2.f * xy + x2 * y2, PB_EPS);
    float arg = sqrtf(nn) / den;
    return 2.f * atanhf(fminf(arg, PB_BND));
}

__global__ __launch_bounds__(512, 1)
void pb_fused_kernel(const float* __restrict__ encoded,
                     const float* __restrict__ n_encoded,
                     const float* __restrict__ mask1,
                     const float* __restrict__ mask2,
                     const float* __restrict__ mask_neg,
                     const float* __restrict__ W,
                     float* __restrict__ out)
{
    const int b    = blockIdx.x;
    const int tid  = threadIdx.x;
    const int wid  = tid >> 5;
    const int lane = tid & 31;

    __shared__ int    s_pos[6];
    __shared__ float4 xs4[6][PB_H4];   // gathered raw token vectors
    __shared__ float  s_part[6][6];    // [gather-warp][vec] partial sumsq
    __shared__ float  s_scale[6];      // expmap0 scale tanh(n)/n
    __shared__ float  s_xn[6];         // clip(||y||, EPS)
    __shared__ float  mxs[6][PB_D];    // matvec results -> final vectors
    __shared__ float  s_term[6];       // e_neg0..3, e_pos, angle

    // ---- 1. one-hot position lookup (S = 256, first 8 warps) ----
    if (tid < PB_S) {
        if (mask1[(size_t)b * PB_S + tid] > 0.5f) s_pos[0] = tid;
        if (mask2[(size_t)b * PB_S + tid] > 0.5f) s_pos[1] = tid;
#pragma unroll
        for (int k = 0; k < PB_NEG; k++)
            if (mask_neg[(size_t)(b * PB_NEG + k) * PB_S + tid] > 0.5f)
                s_pos[2 + k] = tid;
    }
    __syncthreads();

    // ---- 2. gather 6 rows (float4) into smem + sum of squares (warps 0-5) ----
    if (tid < PB_H4) {
        const float4* xrow[6];
        xrow[0] = (const float4*)(encoded + ((size_t)b * PB_S + s_pos[0]) * PB_H);
        xrow[1] = (const float4*)(encoded + ((size_t)b * PB_S + s_pos[1]) * PB_H);
#pragma unroll
        for (int k = 0; k < PB_NEG; k++)
            xrow[2 + k] = (const float4*)(n_encoded +
                          ((size_t)(b * PB_NEG + k) * PB_S + s_pos[2 + k]) * PB_H);

        float ss[6];
#pragma unroll
        for (int j = 0; j < 6; j++) {
            float4 v = xrow[j][tid];
            xs4[j][tid] = v;
            ss[j] = v.x * v.x + v.y * v.y + v.z * v.z + v.w * v.w;
        }
#pragma unroll
        for (int j = 0; j < 6; j++) ss[j] = warp_sum(ss[j]);
        if (lane == 0) {
#pragma unroll
            for (int j = 0; j < 6; j++) s_part[wid][j] = ss[j];
        }
    }
    __syncthreads();

    // ---- 3. expmap0 scales ----
    if (wid == 0 && lane < 6) {
        float t = 0.f;
#pragma unroll
        for (int w = 0; w < 6; w++) t += s_part[w][lane];
        float nrm = sqrtf(t);
        float ncl = fmaxf(nrm, PB_EPS);
        float sc  = tanhf(ncl) / ncl;
        s_scale[lane] = sc;
        s_xn[lane]    = fmaxf(sc * nrm, PB_EPS);
    }
    __syncthreads();

    // ---- 4. shared matvec: warp w -> dims [w*4, w*4+4) for all 6 vectors ----
    const ulonglong2* Wu = (const ulonglong2*)W;           // [D][H4]
    const ulonglong2* xu[6];
#pragma unroll
    for (int j = 0; j < 6; j++) xu[j] = (const ulonglong2*)xs4[j];

    {
        const int dbase = wid * 4;
        u64 acc[4][6];
#pragma unroll
        for (int dd = 0; dd < 4; dd++)
#pragma unroll
            for (int j = 0; j < 6; j++) acc[dd][j] = 0ull;

#pragma unroll
        for (int i = 0; i < PB_H4 / 32; i++) {             // 6 iterations
            const int c = lane + i * 32;
            ulonglong2 xv[6];
#pragma unroll
            for (int j = 0; j < 6; j++) xv[j] = xu[j][c];  // LDS.128
#pragma unroll
            for (int dd = 0; dd < 4; dd++) {
                ulonglong2 wv = Wu[(size_t)(dbase + dd) * PB_H4 + c];  // LDG.128
#pragma unroll
                for (int j = 0; j < 6; j++) {
                    fma_x2(acc[dd][j], wv.x, xv[j].x, acc[dd][j]);
                    fma_x2(acc[dd][j], wv.y, xv[j].y, acc[dd][j]);
                }
            }
        }

#pragma unroll
        for (int dd = 0; dd < 4; dd++) {
            float r0 = warp_sum(x2_hsum(acc[dd][0]));
            float r1 = warp_sum(x2_hsum(acc[dd][1]));
            float r2 = warp_sum(x2_hsum(acc[dd][2]));
            float r3 = warp_sum(x2_hsum(acc[dd][3]));
            float r4 = warp_sum(x2_hsum(acc[dd][4]));
            float r5 = warp_sum(x2_hsum(acc[dd][5]));
            if (lane == 0) {
                mxs[0][dbase + dd] = r0 * s_scale[0];
                mxs[1][dbase + dd] = r1 * s_scale[1];
                mxs[2][dbase + dd] = r2 * s_scale[2];
                mxs[3][dbase + dd] = r3 * s_scale[3];
                mxs[4][dbase + dd] = r4 * s_scale[4];
                mxs[5][dbase + dd] = r5 * s_scale[5];
            }
        }
    }
    __syncthreads();

    // ---- 5. mobius_matvec rescale, in place (6 warps in parallel) ----
    if (wid < 6) {
        float m0 = mxs[wid][lane];
        float m1 = mxs[wid][lane + 32];
        float t  = warp_sum(m0 * m0 + m1 * m1);
        float mn = fmaxf(sqrtf(t), PB_EPS);
        float xn = s_xn[wid];
        float fac = tanhf(mn / xn * atanhf(fminf(xn, PB_BND))) / mn;
        mxs[wid][lane]      = m0 * fac;
        mxs[wid][lane + 32] = m1 * fac;
    }
    __syncthreads();

    // ---- 6. epilogue: 6 warps compute angle + 5 distances in parallel ----
    if (wid < 6) {
        float u0  = mxs[0][lane];
        float u1  = mxs[0][lane + 32];
        float nu2 = warp_sum(u0 * u0 + u1 * u1);

        if (wid < 4) {                      // negative distances
            float w0 = mxs[2 + wid][lane];
            float w1 = mxs[2 + wid][lane + 32];
            float y2 = warp_sum(w0 * w0 + w1 * w1);
            float dn = warp_sum(u0 * w0 + u1 * w1);
            float dk = pb_dist(u0, u1, w0, w1, nu2, y2, dn);
            if (lane == 0) s_term[wid] = expf(-dk);
        } else if (wid == 4) {              // positive-pair distance
            float v0  = mxs[1][lane];
            float v1  = mxs[1][lane + 32];
            float nv2 = warp_sum(v0 * v0 + v1 * v1);
            float duv = warp_sum(u0 * v0 + u1 * v1);
            float dp  = pb_dist(u0, u1, v0, v1, nu2, nv2, duv);
            if (lane == 0) s_term[4] = expf(-dp);
        } else {                            // wid == 5: angle term
            float v0  = mxs[1][lane];
            float v1  = mxs[1][lane + 32];
            float nv2 = warp_sum(v0 * v0 + v1 * v1);
            float duv = warp_sum(u0 * v0 + u1 * v1);
            float d0  = u0 - v0, d1 = u1 - v1;
            float e2  = warp_sum(d0 * d0 + d1 * d1);
            float norm_v = sqrtf(nv2);
            float euclid = sqrtf(e2);
            float rad = fmaxf(1.f + nu2 * nv2 - 2.f * duv, PB_EPS);
            float den = fmaxf(norm_v * euclid * sqrtf(rad), PB_EPS);
            float ca  = (duv * (1.f + nv2) - nv2 * (1.f + nu2)) / den;
            ca = fminf(fmaxf(ca, -PB_BND), PB_BND);
            if (lane == 0) s_term[5] = acosf(ca);
        }
    }
    __syncthreads();

    // ---- 7. combine + accumulate mean (alpha=0.5 => both weights are 1) ----
    if (tid == 0) {
        float Z1 = s_term[0] + s_term[1] + s_term[2] + s_term[3];
        float ep = s_term[4];
        float ns = -logf(ep / (Z1 + ep));
        atomicAdd(out, (s_term[5] + ns) * (1.0f / PB_B));
    }
}

extern "C" void kernel_launch(void* const* d_in, const int* in_sizes, int n_in,
                              void* d_out, int out_size)
{
    const float* encoded   = (const float*)d_in[0];
    const float* n_encoded = (const float*)d_in[1];
    const float* mask1     = (const float*)d_in[2];
    const float* mask2     = (const float*)d_in[3];
    const float* mask_neg  = (const float*)d_in[4];
    const float* W         = (const float*)d_in[5];
    float* out = (float*)d_out;

    cudaMemsetAsync(out, 0, sizeof(float));
    pb_fused_kernel<<<PB_B, 512>>>(encoded, n_encoded,
                                   mask1, mask2, mask_neg, W, out);
}